// round 15
// baseline (speedup 1.0000x reference)
#include <cuda_runtime.h>
#include <math.h>
#include <float.h>

// Problem capacities (B=32, N=300, M=60, L=5, C=1000)
#define CAP_B 32
#define CAP_N 300
#define CAP_M 60
#define HT 320             // block threads (>= CAP_N), one column per thread
#define NWARP (HT / 32)

// ---------------- device scratch (no allocations allowed) ----------------
__device__ int      g_k[CAP_B];
__device__ double   g_cls[CAP_B];
__device__ double   g_pair[CAP_B * 6];   // {bbox, giou, aux_bbox, aux_giou, bce, aux_bce}
__device__ unsigned g_sem;               // zero-init; reset by last block each run

// ---------------- helpers ----------------
__device__ __forceinline__ float giou_f(
    float ax0, float ay0, float ax1, float ay1,
    float bx0, float by0, float bx1, float by1)
{
    const float EPS = 1e-7f;
    float area_a = (ax1 - ax0) * (ay1 - ay0);
    float area_b = (bx1 - bx0) * (by1 - by0);
    float ltx = fmaxf(ax0, bx0), lty = fmaxf(ay0, by0);
    float rbx = fminf(ax1, bx1), rby = fminf(ay1, by1);
    float wx = fmaxf(rbx - ltx, 0.0f), wy = fmaxf(rby - lty, 0.0f);
    float inter = wx * wy;
    float uni = area_a + area_b - inter;
    float iou = inter / (uni + EPS);
    float ex = fmaxf(fmaxf(ax1, bx1) - fminf(ax0, bx0), 0.0f);
    float ey = fmaxf(fmaxf(ay1, by1) - fminf(ay0, by0), 0.0f);
    float enc = ex * ey;
    return iou - (enc - uni) / (enc + EPS);
}

__device__ __forceinline__ float giou_cxcywh(float4 p, float4 q)
{
    return giou_f(p.x - p.z * 0.5f, p.y - p.w * 0.5f, p.x + p.z * 0.5f, p.y + p.w * 0.5f,
                  q.x - q.z * 0.5f, q.y - q.w * 0.5f, q.x + q.z * 0.5f, q.y + q.w * 0.5f);
}

__device__ __forceinline__ float l1_cxcywh(float4 p, float4 q)
{
    return fabsf(p.x - q.x) + fabsf(p.y - q.y) + fabsf(p.z - q.z) + fabsf(p.w - q.w);
}

__device__ __forceinline__ float bce_f(float x, float t)
{
    return fmaxf(x, 0.0f) - x * t + log1pf(expf(-fabsf(x)));
}

__device__ __forceinline__ unsigned order_f32(float f)
{
    unsigned u = __float_as_uint(f);
    return (u & 0x80000000u) ? ~u : (u | 0x80000000u);
}
__device__ __forceinline__ float unorder_f32(unsigned k)
{
    unsigned u = (k & 0x80000000u) ? (k & 0x7fffffffu) : ~k;
    return __uint_as_float(u);
}
__device__ __forceinline__ unsigned long long pack_vc(float v, unsigned col)
{
    return ((unsigned long long)order_f32(v) << 32) | (unsigned long long)col;
}

// ---------------- single fused kernel: LAP + all losses + final fold --------------
__global__ void __launch_bounds__(HT, 1)
detr_kernel(const float* __restrict__ mask,
            const float4* __restrict__ pred,
            const float4* __restrict__ tgt,
            const float4* __restrict__ aux_pred,
            const float* __restrict__ obj,
            const float* __restrict__ aux_obj,
            const float* __restrict__ cls,
            const int* __restrict__ label,
            float* __restrict__ out,
            int B, int N, int M, int L, int C)
{
    extern __shared__ float cost_sh[];               // [k][N] row-major
    const unsigned FULL = 0xffffffffu;
    int b = blockIdx.x;
    int tid = threadIdx.x;
    int lane = tid & 31, wid = tid >> 5;
    int col = tid;
    bool active = (col < N);

    __shared__ float4 pred_sh[CAP_N];
    __shared__ float4 tgt_sh[CAP_M];
    __shared__ float  u_sh[CAP_M];
    __shared__ float  margin_sh[CAP_M];
    __shared__ int    gcol_sh[CAP_M];
    __shared__ int    vid_sh[CAP_M];
    __shared__ int    row4col_sh[CAP_N];   // col -> row (0-based), -1 free
    __shared__ int    col4row_sh[CAP_M];   // row -> col, -1 free
    __shared__ int2   way_pack_sh[CAP_N];  // {pred row, pred row's column} at pop time
    __shared__ int    queue_sh[CAP_M + 4];
    __shared__ alignas(16) unsigned long long wpack_sh[2][NWARP];
    __shared__ float  f_red[NWARP];
    __shared__ int    s_k, s_nf, s_last;
    __shared__ double s_red[6 * NWARP];

    if (active) row4col_sh[col] = -1;
    if (tid < M) col4row_sh[tid] = -1;
    for (int j = tid; j < N; j += HT) pred_sh[j] = pred[b * N + j];
    for (int t = tid; t < M; t += HT) tgt_sh[t] = tgt[b * M + t];

    const float* mrow = mask + (size_t)b * M;
    if (wid == 0) {
        bool v0 = (lane < M) && (mrow[lane] > 0.5f);
        bool v1 = (32 + lane < M) && (mrow[32 + lane] > 0.5f);
        unsigned b0 = __ballot_sync(FULL, v0);
        unsigned b1 = __ballot_sync(FULL, v1);
        unsigned lm = (1u << lane) - 1u;
        if (v0) vid_sh[__popc(b0 & lm)] = lane;
        if (v1) vid_sh[__popc(b0) + __popc(b1 & lm)] = 32 + lane;
        if (lane == 0) {
            s_k = __popc(b0) + __popc(b1);
            g_k[b] = s_k;
        }
    }

    // --- cls log-softmax for this batch ---
    const float* xr = cls + (size_t)b * C;
    float cm = -FLT_MAX;
    for (int c = tid; c < C; c += HT) cm = fmaxf(cm, xr[c]);
    #pragma unroll
    for (int off = 16; off; off >>= 1)
        cm = fmaxf(cm, __shfl_xor_sync(FULL, cm, off));
    if (lane == 0) f_red[wid] = cm;
    __syncthreads();
    {
        float m0 = f_red[0];
        #pragma unroll
        for (int w = 1; w < NWARP; w++) m0 = fmaxf(m0, f_red[w]);
        cm = m0;
    }
    float cs = 0.0f;
    for (int c = tid; c < C; c += HT) cs += expf(xr[c] - cm);
    #pragma unroll
    for (int off = 16; off; off >>= 1)
        cs += __shfl_xor_sync(FULL, cs, off);
    __syncthreads();          // f_red reuse
    if (lane == 0) f_red[wid] = cs;
    __syncthreads();
    if (tid == 0) {
        float s0 = 0.0f;
        #pragma unroll
        for (int w = 0; w < NWARP; w++) s0 += f_red[w];
        g_cls[b] = (double)(cm + logf(s0) - xr[label[b]]);
    }
    int k = s_k;

    // --- build cost matrix in smem: cost[i][j] = 5*L1 - 2*GIoU ---
    for (int idx = tid; idx < k * N; idx += HT) {
        int i = idx / N;
        int j = idx - i * N;
        float4 p = pred_sh[j];
        float4 q = tgt_sh[vid_sh[i]];
        cost_sh[idx] = 5.0f * l1_cxcywh(p, q) - 2.0f * giou_cxcywh(p, q);
    }
    __syncthreads();

    // --- greedy: per-row (min1, argmin, min2) — rows striped over warps ---
    for (int i = wid; i < k; i += NWARP) {
        const float* crow = cost_sh + i * N;
        unsigned long long b1 = 0xFFFFFFFFFFFFFFFFull;
        unsigned long long b2 = 0xFFFFFFFFFFFFFFFFull;
        #pragma unroll
        for (int q = 0; q < 10; q++) {
            int c = lane + 32 * q;
            if (c < N) {
                unsigned long long pk = pack_vc(crow[c], (unsigned)c);
                if (pk < b1) { b2 = b1; b1 = pk; }
                else if (pk < b2) b2 = pk;
            }
        }
        #pragma unroll
        for (int off = 16; off; off >>= 1) {
            unsigned long long o1 = __shfl_xor_sync(FULL, b1, off);
            unsigned long long o2 = __shfl_xor_sync(FULL, b2, off);
            unsigned long long hi = (b1 < o1) ? o1 : b1;
            b1 = (b1 < o1) ? b1 : o1;
            unsigned long long lo2 = (b2 < o2) ? b2 : o2;
            b2 = (hi < lo2) ? hi : lo2;
        }
        if (lane == 0) {
            float m1 = unorder_f32((unsigned)(b1 >> 32));
            float m2 = unorder_f32((unsigned)(b2 >> 32));
            u_sh[i] = m1;
            gcol_sh[i] = (int)(b1 & 0xFFFFFFFFull);
            margin_sh[i] = m2 - m1;
        }
    }
    __syncthreads();

    // --- conflict resolution: contested column goes to max-margin row ---
    if (tid == 0) {
        int nf = 0;
        for (int i = 0; i < k; i++) {
            int c = gcol_sh[i];
            int own = row4col_sh[c];
            if (own < 0) {
                row4col_sh[c] = i; col4row_sh[i] = c;
            } else if (margin_sh[i] > margin_sh[own]) {
                row4col_sh[c] = i; col4row_sh[i] = c;
                col4row_sh[own] = -1;
                queue_sh[nf++] = own;
            } else {
                queue_sh[nf++] = i;
            }
        }
        s_nf = nf;
    }
    __syncthreads();
    int nf = s_nf;

    // --- block-wide SSP augmentation: ONE barrier per Dijkstra step ---
    // Fold payload carries (col, owner row) so the winning column's row arrives
    // WITH the fold. way_pack also records the predecessor's column at pop time
    // (static during a path), so rewiring needs ONE LDS per hop.
    float v = 0.0f;  // column dual (register; one col per thread)
    int par = 0;
    int r4c = active ? row4col_sh[col] : -1;
    for (int qi = 0; qi < nf; qi++) {
        int cur = queue_sh[qi];
        float minv = INFINITY;
        int way = 0;
        bool inSC = false;
        int i_cur = cur;
        float base = -u_sh[cur];
        float mv;
        int sink;
        unsigned payload = ((unsigned)col << 7) | (unsigned)(r4c + 1);
        while (true) {
            unsigned key = 0xFFFFFFFFu;
            if (active && !inSC) {
                float r = base + cost_sh[i_cur * N + col] - v;
                if (r < minv) { minv = r; way = i_cur; }
                key = order_f32(minv);
            }
            unsigned kmin = __reduce_min_sync(FULL, key);
            unsigned cnd = (key == kmin) ? payload : 0xFFFFFFFFu;
            unsigned cmin = __reduce_min_sync(FULL, cnd);
            if (lane == 0)
                wpack_sh[par][wid] = ((unsigned long long)kmin << 32) | cmin;
            __syncthreads();
            // vectorized pairwise tree fold of NWARP(=10) candidates
            const ulonglong2* wp2 =
                reinterpret_cast<const ulonglong2*>(&wpack_sh[par][0]);
            ulonglong2 p01 = wp2[0];
            ulonglong2 p23 = wp2[1];
            ulonglong2 p45 = wp2[2];
            ulonglong2 p67 = wp2[3];
            ulonglong2 p89 = wp2[4];
            unsigned long long c0 = (p01.y < p01.x) ? p01.y : p01.x;
            unsigned long long c2 = (p23.y < p23.x) ? p23.y : p23.x;
            unsigned long long c4 = (p45.y < p45.x) ? p45.y : p45.x;
            unsigned long long c6 = (p67.y < p67.x) ? p67.y : p67.x;
            unsigned long long c8 = (p89.y < p89.x) ? p89.y : p89.x;
            c0 = (c2 < c0) ? c2 : c0;
            c4 = (c6 < c4) ? c6 : c4;
            c0 = (c4 < c0) ? c4 : c0;
            unsigned long long best = (c8 < c0) ? c8 : c0;
            par ^= 1;
            float d = unorder_f32((unsigned)(best >> 32));
            unsigned pay = (unsigned)(best & 0xFFFFFFFFull);
            int j0 = (int)(pay >> 7);
            int r0 = (int)(pay & 0x7Fu) - 1;
            if (col == j0) {
                inSC = true;
                // record predecessor row AND its current column (static in-path)
                int jn = (way == cur) ? -1 : col4row_sh[way];
                way_pack_sh[col] = make_int2(way, jn);
            }
            if (r0 < 0) { mv = d; sink = j0; break; }
            base = d - u_sh[r0];           // u load runs parallel with next cost load
            i_cur = r0;
        }
        __syncthreads();   // way_pack[sink] + loop reads done before dual/assign updates
        // dual updates (once per augmentation)
        if (active && inSC) {
            float diff = mv - minv;
            v -= diff;
            if (r4c >= 0) u_sh[r4c] += diff;   // distinct row per col
        }
        if (tid == 0) u_sh[cur] += mv;
        __syncthreads();   // duals settled before assignment rewiring
        if (tid == 0) {
            int j = sink;
            while (true) {
                int2 pk = way_pack_sh[j];      // one LDS per hop
                row4col_sh[j] = pk.x;
                col4row_sh[pk.x] = j;
                if (pk.x == cur) break;
                j = pk.y;
            }
        }
        __syncthreads();
        if (active) r4c = row4col_sh[col];   // refresh after rewiring
    }

    // --- pair losses + BCE (one column per thread) ---
    double bb = 0.0, gg = 0.0, ab = 0.0, ag = 0.0, bm = 0.0, ba = 0.0;
    if (active) {
        int r = r4c;
        float ot = (r >= 0) ? 1.0f : 0.0f;
        bm = (double)bce_f(obj[b * N + col], ot);
        for (int l = 0; l < L; l++)
            ba += (double)bce_f(aux_obj[((size_t)l * B + b) * N + col], ot);
        if (r >= 0) {
            float4 p = pred_sh[col];
            float4 t = tgt_sh[vid_sh[r]];
            bb = (double)l1_cxcywh(p, t);
            gg = (double)(1.0f - giou_cxcywh(p, t));
            for (int l = 0; l < L; l++) {
                float4 a = aux_pred[((size_t)l * B + b) * N + col];
                ab += (double)l1_cxcywh(a, t);
                ag += (double)(1.0f - giou_cxcywh(a, t));
            }
        }
    }
    #pragma unroll
    for (int off = 16; off; off >>= 1) {
        bb += __shfl_xor_sync(FULL, bb, off);
        gg += __shfl_xor_sync(FULL, gg, off);
        ab += __shfl_xor_sync(FULL, ab, off);
        ag += __shfl_xor_sync(FULL, ag, off);
        bm += __shfl_xor_sync(FULL, bm, off);
        ba += __shfl_xor_sync(FULL, ba, off);
    }
    if (lane == 0) {
        s_red[wid] = bb;
        s_red[NWARP + wid] = gg;
        s_red[2 * NWARP + wid] = ab;
        s_red[3 * NWARP + wid] = ag;
        s_red[4 * NWARP + wid] = bm;
        s_red[5 * NWARP + wid] = ba;
    }
    __syncthreads();
    if (tid < 6) {
        double t0 = 0.0;
        #pragma unroll
        for (int w = 0; w < NWARP; w++) t0 += s_red[tid * NWARP + w];
        g_pair[b * 6 + tid] = t0;
    }

    // --- last block folds everything into the output scalar ---
    if (tid == 0) {
        __threadfence();
        unsigned t = atomicAdd(&g_sem, 1u);
        s_last = (t == (unsigned)(B - 1)) ? 1 : 0;
    }
    __syncthreads();
    if (!s_last) return;
    __threadfence();
    if (tid == 0) {
        double nb = 0.0, clsl = 0.0, bbox = 0.0, gi = 0.0;
        double abx = 0.0, agx = 0.0, objs = 0.0, aobj = 0.0;
        for (int bi = 0; bi < B; bi++) {
            nb   += (double)g_k[bi];
            clsl += g_cls[bi];
            bbox += g_pair[bi * 6 + 0];
            gi   += g_pair[bi * 6 + 1];
            abx  += g_pair[bi * 6 + 2];
            agx  += g_pair[bi * 6 + 3];
            objs += g_pair[bi * 6 + 4];
            aobj += g_pair[bi * 6 + 5];
        }
        if (nb < 1.0) nb = 1.0;
        double BN = (double)B * (double)N;
        double tot = clsl / (double)B
                   + 5.0 * bbox / nb
                   + 2.0 * gi / nb
                   + objs / BN
                   + (5.0 * abx / nb + 2.0 * agx / nb + aobj / BN) * 0.5 / (double)L;
        out[0] = (float)tot;
        g_sem = 0u;  // reset for next replay
    }
}

// ---------------- launch ----------------
extern "C" void kernel_launch(void* const* d_in, const int* in_sizes, int n_in,
                              void* d_out, int out_size)
{
    const float* cls      = (const float*)d_in[0];
    const int*   label    = (const int*)d_in[1];
    const float* pred     = (const float*)d_in[2];
    const float* obj      = (const float*)d_in[3];
    const float* tgt      = (const float*)d_in[4];
    const float* mask     = (const float*)d_in[5];
    const float* aux_pred = (const float*)d_in[6];
    const float* aux_obj  = (const float*)d_in[7];

    int B = in_sizes[1];
    int C = in_sizes[0] / B;
    int N = in_sizes[3] / B;
    int M = in_sizes[5] / B;
    int L = in_sizes[6] / (B * N * 4);
    float* out = (float*)d_out;

    size_t smem = (size_t)CAP_M * CAP_N * sizeof(float);  // 72000 B
    static int attr_set = 0;
    if (!attr_set) {
        cudaFuncSetAttribute(detr_kernel,
                             cudaFuncAttributeMaxDynamicSharedMemorySize, (int)smem);
        attr_set = 1;
    }

    detr_kernel<<<B, HT, smem>>>(mask, (const float4*)pred, (const float4*)tgt,
                                 (const float4*)aux_pred, obj, aux_obj,
                                 cls, label, out, B, N, M, L, C);
}

// round 16
// speedup vs baseline: 1.0586x; 1.0586x over previous
#include <cuda_runtime.h>
#include <math.h>
#include <float.h>

// Problem capacities (B=32, N=300, M=60, L=5, C=1000)
#define CAP_B 32
#define CAP_N 300
#define CAP_M 60
#define HT 320             // block threads (>= CAP_N), one column per thread
#define NWARP (HT / 32)

// ---------------- device scratch (no allocations allowed) ----------------
__device__ int      g_k[CAP_B];
__device__ double   g_cls[CAP_B];
__device__ double   g_pair[CAP_B * 6];   // {bbox, giou, aux_bbox, aux_giou, bce, aux_bce}
__device__ unsigned g_sem;               // zero-init; reset by last block each run

// ---------------- helpers ----------------
__device__ __forceinline__ float giou_f(
    float ax0, float ay0, float ax1, float ay1,
    float bx0, float by0, float bx1, float by1)
{
    const float EPS = 1e-7f;
    float area_a = (ax1 - ax0) * (ay1 - ay0);
    float area_b = (bx1 - bx0) * (by1 - by0);
    float ltx = fmaxf(ax0, bx0), lty = fmaxf(ay0, by0);
    float rbx = fminf(ax1, bx1), rby = fminf(ay1, by1);
    float wx = fmaxf(rbx - ltx, 0.0f), wy = fmaxf(rby - lty, 0.0f);
    float inter = wx * wy;
    float uni = area_a + area_b - inter;
    float iou = inter / (uni + EPS);
    float ex = fmaxf(fmaxf(ax1, bx1) - fminf(ax0, bx0), 0.0f);
    float ey = fmaxf(fmaxf(ay1, by1) - fminf(ay0, by0), 0.0f);
    float enc = ex * ey;
    return iou - (enc - uni) / (enc + EPS);
}

__device__ __forceinline__ float giou_cxcywh(float4 p, float4 q)
{
    return giou_f(p.x - p.z * 0.5f, p.y - p.w * 0.5f, p.x + p.z * 0.5f, p.y + p.w * 0.5f,
                  q.x - q.z * 0.5f, q.y - q.w * 0.5f, q.x + q.z * 0.5f, q.y + q.w * 0.5f);
}

__device__ __forceinline__ float l1_cxcywh(float4 p, float4 q)
{
    return fabsf(p.x - q.x) + fabsf(p.y - q.y) + fabsf(p.z - q.z) + fabsf(p.w - q.w);
}

__device__ __forceinline__ float bce_f(float x, float t)
{
    return fmaxf(x, 0.0f) - x * t + log1pf(expf(-fabsf(x)));
}

__device__ __forceinline__ unsigned order_f32(float f)
{
    unsigned u = __float_as_uint(f);
    return (u & 0x80000000u) ? ~u : (u | 0x80000000u);
}
__device__ __forceinline__ float unorder_f32(unsigned k)
{
    unsigned u = (k & 0x80000000u) ? (k & 0x7fffffffu) : ~k;
    return __uint_as_float(u);
}
__device__ __forceinline__ unsigned long long pack_vc(float v, unsigned col)
{
    return ((unsigned long long)order_f32(v) << 32) | (unsigned long long)col;
}

// ---------------- single fused kernel: LAP + all losses + final fold --------------
__global__ void __launch_bounds__(HT, 1)
detr_kernel(const float* __restrict__ mask,
            const float4* __restrict__ pred,
            const float4* __restrict__ tgt,
            const float4* __restrict__ aux_pred,
            const float* __restrict__ obj,
            const float* __restrict__ aux_obj,
            const float* __restrict__ cls,
            const int* __restrict__ label,
            float* __restrict__ out,
            int B, int N, int M, int L, int C)
{
    extern __shared__ float cost_sh[];               // [k][N] row-major
    const unsigned FULL = 0xffffffffu;
    int b = blockIdx.x;
    int tid = threadIdx.x;
    int lane = tid & 31, wid = tid >> 5;
    int col = tid;
    bool active = (col < N);

    __shared__ float4 pred_sh[CAP_N];
    __shared__ float4 tgt_sh[CAP_M];
    __shared__ float  u_sh[CAP_M];
    __shared__ float  margin_sh[CAP_M];
    __shared__ int    gcol_sh[CAP_M];
    __shared__ int    vid_sh[CAP_M];
    __shared__ int    row4col_sh[CAP_N];   // col -> row (0-based), -1 free
    __shared__ int    col4row_sh[CAP_M];   // row -> col, -1 free
    __shared__ int    way_sh[CAP_N];       // predecessor row along shortest path
    __shared__ int    queue_sh[CAP_M + 4];
    __shared__ unsigned long long wpack_sh[2][NWARP];
    __shared__ float  f_red[NWARP];
    __shared__ int    s_k, s_nf, s_last;
    __shared__ double s_red[6 * NWARP];

    if (active) row4col_sh[col] = -1;
    if (tid < M) col4row_sh[tid] = -1;
    for (int j = tid; j < N; j += HT) pred_sh[j] = pred[b * N + j];
    for (int t = tid; t < M; t += HT) tgt_sh[t] = tgt[b * M + t];

    const float* mrow = mask + (size_t)b * M;
    if (wid == 0) {
        bool v0 = (lane < M) && (mrow[lane] > 0.5f);
        bool v1 = (32 + lane < M) && (mrow[32 + lane] > 0.5f);
        unsigned b0 = __ballot_sync(FULL, v0);
        unsigned b1 = __ballot_sync(FULL, v1);
        unsigned lm = (1u << lane) - 1u;
        if (v0) vid_sh[__popc(b0 & lm)] = lane;
        if (v1) vid_sh[__popc(b0) + __popc(b1 & lm)] = 32 + lane;
        if (lane == 0) {
            s_k = __popc(b0) + __popc(b1);
            g_k[b] = s_k;
        }
    }

    // --- cls log-softmax for this batch ---
    const float* xr = cls + (size_t)b * C;
    float cm = -FLT_MAX;
    for (int c = tid; c < C; c += HT) cm = fmaxf(cm, xr[c]);
    #pragma unroll
    for (int off = 16; off; off >>= 1)
        cm = fmaxf(cm, __shfl_xor_sync(FULL, cm, off));
    if (lane == 0) f_red[wid] = cm;
    __syncthreads();
    {
        float m0 = f_red[0];
        #pragma unroll
        for (int w = 1; w < NWARP; w++) m0 = fmaxf(m0, f_red[w]);
        cm = m0;
    }
    float cs = 0.0f;
    for (int c = tid; c < C; c += HT) cs += expf(xr[c] - cm);
    #pragma unroll
    for (int off = 16; off; off >>= 1)
        cs += __shfl_xor_sync(FULL, cs, off);
    __syncthreads();          // f_red reuse
    if (lane == 0) f_red[wid] = cs;
    __syncthreads();
    if (tid == 0) {
        float s0 = 0.0f;
        #pragma unroll
        for (int w = 0; w < NWARP; w++) s0 += f_red[w];
        g_cls[b] = (double)(cm + logf(s0) - xr[label[b]]);
    }
    int k = s_k;

    // --- build cost matrix in smem: cost[i][j] = 5*L1 - 2*GIoU ---
    for (int idx = tid; idx < k * N; idx += HT) {
        int i = idx / N;
        int j = idx - i * N;
        float4 p = pred_sh[j];
        float4 q = tgt_sh[vid_sh[i]];
        cost_sh[idx] = 5.0f * l1_cxcywh(p, q) - 2.0f * giou_cxcywh(p, q);
    }
    __syncthreads();

    // --- greedy: per-row (min1, argmin, min2) — rows striped over warps ---
    for (int i = wid; i < k; i += NWARP) {
        const float* crow = cost_sh + i * N;
        unsigned long long b1 = 0xFFFFFFFFFFFFFFFFull;
        unsigned long long b2 = 0xFFFFFFFFFFFFFFFFull;
        #pragma unroll
        for (int q = 0; q < 10; q++) {
            int c = lane + 32 * q;
            if (c < N) {
                unsigned long long pk = pack_vc(crow[c], (unsigned)c);
                if (pk < b1) { b2 = b1; b1 = pk; }
                else if (pk < b2) b2 = pk;
            }
        }
        #pragma unroll
        for (int off = 16; off; off >>= 1) {
            unsigned long long o1 = __shfl_xor_sync(FULL, b1, off);
            unsigned long long o2 = __shfl_xor_sync(FULL, b2, off);
            unsigned long long hi = (b1 < o1) ? o1 : b1;
            b1 = (b1 < o1) ? b1 : o1;
            unsigned long long lo2 = (b2 < o2) ? b2 : o2;
            b2 = (hi < lo2) ? hi : lo2;
        }
        if (lane == 0) {
            float m1 = unorder_f32((unsigned)(b1 >> 32));
            float m2 = unorder_f32((unsigned)(b2 >> 32));
            u_sh[i] = m1;
            gcol_sh[i] = (int)(b1 & 0xFFFFFFFFull);
            margin_sh[i] = m2 - m1;
        }
    }
    __syncthreads();

    // --- conflict resolution: contested column goes to max-margin row ---
    if (tid == 0) {
        int nf = 0;
        for (int i = 0; i < k; i++) {
            int c = gcol_sh[i];
            int own = row4col_sh[c];
            if (own < 0) {
                row4col_sh[c] = i; col4row_sh[i] = c;
            } else if (margin_sh[i] > margin_sh[own]) {
                row4col_sh[c] = i; col4row_sh[i] = c;
                col4row_sh[own] = -1;
                queue_sh[nf++] = own;
            } else {
                queue_sh[nf++] = i;
            }
        }
        s_nf = nf;
    }
    __syncthreads();
    int nf = s_nf;

    // --- block-wide SSP augmentation: ONE barrier per Dijkstra step ---
    // Fold payload carries (col, owner row) so the winning column's row arrives
    // WITH the fold, removing the dependent row4col[j0] LDS from the step chain.
    float v = 0.0f;  // column dual (register; one col per thread)
    int par = 0;
    int r4c = active ? row4col_sh[col] : -1;
    for (int qi = 0; qi < nf; qi++) {
        int cur = queue_sh[qi];
        float minv = INFINITY;
        int way = 0;
        bool inSC = false;
        int i_cur = cur;
        float base = -u_sh[cur];
        float mv;
        int sink;
        unsigned payload = ((unsigned)col << 7) | (unsigned)(r4c + 1);
        while (true) {
            unsigned key = 0xFFFFFFFFu;
            if (active && !inSC) {
                float r = base + cost_sh[i_cur * N + col] - v;
                if (r < minv) { minv = r; way = i_cur; }
                key = order_f32(minv);
            }
            unsigned kmin = __reduce_min_sync(FULL, key);
            unsigned cnd = (key == kmin) ? payload : 0xFFFFFFFFu;
            unsigned cmin = __reduce_min_sync(FULL, cnd);
            if (lane == 0)
                wpack_sh[par][wid] = ((unsigned long long)kmin << 32) | cmin;
            __syncthreads();
            // pairwise tree fold of NWARP(=10) candidates
            unsigned long long c0 = wpack_sh[par][0];
            unsigned long long c1 = wpack_sh[par][1];
            unsigned long long c2 = wpack_sh[par][2];
            unsigned long long c3 = wpack_sh[par][3];
            unsigned long long c4 = wpack_sh[par][4];
            unsigned long long c5 = wpack_sh[par][5];
            unsigned long long c6 = wpack_sh[par][6];
            unsigned long long c7 = wpack_sh[par][7];
            unsigned long long c8 = wpack_sh[par][8];
            unsigned long long c9 = wpack_sh[par][9];
            c0 = (c1 < c0) ? c1 : c0;
            c2 = (c3 < c2) ? c3 : c2;
            c4 = (c5 < c4) ? c5 : c4;
            c6 = (c7 < c6) ? c7 : c6;
            c8 = (c9 < c8) ? c9 : c8;
            c0 = (c2 < c0) ? c2 : c0;
            c4 = (c6 < c4) ? c6 : c4;
            c0 = (c4 < c0) ? c4 : c0;
            unsigned long long best = (c8 < c0) ? c8 : c0;
            par ^= 1;
            float d = unorder_f32((unsigned)(best >> 32));
            unsigned pay = (unsigned)(best & 0xFFFFFFFFull);
            int j0 = (int)(pay >> 7);
            int r0 = (int)(pay & 0x7Fu) - 1;
            if (col == j0) { inSC = true; way_sh[col] = way; }
            if (r0 < 0) { mv = d; sink = j0; break; }
            base = d - u_sh[r0];           // u load runs parallel with next cost load
            i_cur = r0;
        }
        __syncthreads();   // way_sh writes + scan reads complete
        // MERGED phase: dual updates (register-indexed, disjoint rows) run
        // concurrently with tid0's path rewiring (disjoint write sets:
        // u_sh vs row4col/col4row; r4c==cur impossible since cur was free).
        if (active && inSC) {
            float diff = mv - minv;
            v -= diff;
            if (r4c >= 0) u_sh[r4c] += diff;   // distinct row per col
        }
        if (tid == 0) {
            u_sh[cur] += mv;
            int j = sink;
            while (true) {
                int i = way_sh[j];
                row4col_sh[j] = i;
                int jn = col4row_sh[i];
                col4row_sh[i] = j;
                if (i == cur) break;
                j = jn;
            }
        }
        __syncthreads();
        if (active) r4c = row4col_sh[col];   // refresh after rewiring
    }

    // --- pair losses + BCE (one column per thread) ---
    double bb = 0.0, gg = 0.0, ab = 0.0, ag = 0.0, bm = 0.0, ba = 0.0;
    if (active) {
        int r = r4c;
        float ot = (r >= 0) ? 1.0f : 0.0f;
        bm = (double)bce_f(obj[b * N + col], ot);
        for (int l = 0; l < L; l++)
            ba += (double)bce_f(aux_obj[((size_t)l * B + b) * N + col], ot);
        if (r >= 0) {
            float4 p = pred_sh[col];
            float4 t = tgt_sh[vid_sh[r]];
            bb = (double)l1_cxcywh(p, t);
            gg = (double)(1.0f - giou_cxcywh(p, t));
            for (int l = 0; l < L; l++) {
                float4 a = aux_pred[((size_t)l * B + b) * N + col];
                ab += (double)l1_cxcywh(a, t);
                ag += (double)(1.0f - giou_cxcywh(a, t));
            }
        }
    }
    #pragma unroll
    for (int off = 16; off; off >>= 1) {
        bb += __shfl_xor_sync(FULL, bb, off);
        gg += __shfl_xor_sync(FULL, gg, off);
        ab += __shfl_xor_sync(FULL, ab, off);
        ag += __shfl_xor_sync(FULL, ag, off);
        bm += __shfl_xor_sync(FULL, bm, off);
        ba += __shfl_xor_sync(FULL, ba, off);
    }
    if (lane == 0) {
        s_red[wid] = bb;
        s_red[NWARP + wid] = gg;
        s_red[2 * NWARP + wid] = ab;
        s_red[3 * NWARP + wid] = ag;
        s_red[4 * NWARP + wid] = bm;
        s_red[5 * NWARP + wid] = ba;
    }
    __syncthreads();
    if (tid < 6) {
        double t0 = 0.0;
        #pragma unroll
        for (int w = 0; w < NWARP; w++) t0 += s_red[tid * NWARP + w];
        g_pair[b * 6 + tid] = t0;
    }

    // --- last block folds everything into the output scalar ---
    if (tid == 0) {
        __threadfence();
        unsigned t = atomicAdd(&g_sem, 1u);
        s_last = (t == (unsigned)(B - 1)) ? 1 : 0;
    }
    __syncthreads();
    if (!s_last) return;
    __threadfence();
    if (tid == 0) {
        double nb = 0.0, clsl = 0.0, bbox = 0.0, gi = 0.0;
        double abx = 0.0, agx = 0.0, objs = 0.0, aobj = 0.0;
        for (int bi = 0; bi < B; bi++) {
            nb   += (double)g_k[bi];
            clsl += g_cls[bi];
            bbox += g_pair[bi * 6 + 0];
            gi   += g_pair[bi * 6 + 1];
            abx  += g_pair[bi * 6 + 2];
            agx  += g_pair[bi * 6 + 3];
            objs += g_pair[bi * 6 + 4];
            aobj += g_pair[bi * 6 + 5];
        }
        if (nb < 1.0) nb = 1.0;
        double BN = (double)B * (double)N;
        double tot = clsl / (double)B
                   + 5.0 * bbox / nb
                   + 2.0 * gi / nb
                   + objs / BN
                   + (5.0 * abx / nb + 2.0 * agx / nb + aobj / BN) * 0.5 / (double)L;
        out[0] = (float)tot;
        g_sem = 0u;  // reset for next replay
    }
}

// ---------------- launch ----------------
extern "C" void kernel_launch(void* const* d_in, const int* in_sizes, int n_in,
                              void* d_out, int out_size)
{
    const float* cls      = (const float*)d_in[0];
    const int*   label    = (const int*)d_in[1];
    const float* pred     = (const float*)d_in[2];
    const float* obj      = (const float*)d_in[3];
    const float* tgt      = (const float*)d_in[4];
    const float* mask     = (const float*)d_in[5];
    const float* aux_pred = (const float*)d_in[6];
    const float* aux_obj  = (const float*)d_in[7];

    int B = in_sizes[1];
    int C = in_sizes[0] / B;
    int N = in_sizes[3] / B;
    int M = in_sizes[5] / B;
    int L = in_sizes[6] / (B * N * 4);
    float* out = (float*)d_out;

    size_t smem = (size_t)CAP_M * CAP_N * sizeof(float);  // 72000 B
    static int attr_set = 0;
    if (!attr_set) {
        cudaFuncSetAttribute(detr_kernel,
                             cudaFuncAttributeMaxDynamicSharedMemorySize, (int)smem);
        attr_set = 1;
    }

    detr_kernel<<<B, HT, smem>>>(mask, (const float4*)pred, (const float4*)tgt,
                                 (const float4*)aux_pred, obj, aux_obj,
                                 cls, label, out, B, N, M, L, C);
}